// round 13
// baseline (speedup 1.0000x reference)
#include <cuda_runtime.h>
#include <cuda_bf16.h>
#include <math.h>

// Problem constants
#define BB 64
#define TT 128
#define TS 127          // timesteps = T-1
#define VV 10000
#define EE 300
#define HH 1024
#define G4 4096         // 4*H

#define GRID_N 296      // persistent grid: exactly 2 CTAs per SM on 148 SMs
#define NTASK 768       // gemm tasks per slot: L0 64x4=256, L1 64x8=512
#define NSLOT 128
#define SPAD 68         // padded smem row (floats)
#define MROWS (TS * BB) // 8128 logits rows

typedef unsigned long long u64;

// ---------------- scratch (static device memory; no allocations) -------------
__device__ float g_pre0[(size_t)TS * BB * G4];     // x@w_ih0 + b0, row = t*64+b
__device__ float g_h1all[(size_t)TS * BB * HH];    // all layer-1 hidden states
__device__ float g_h0buf[2][BB * HH];
__device__ float g_c0[BB * HH];
__device__ float g_c1[BB * HH];
__device__ float g_zero[BB * HH];                  // stays zero (never written)
__device__ float g_P0[4][BB * G4];                 // L0 K-chunk partials
__device__ float g_P1[8][BB * G4];                 // L1 K-chunk partials
__device__ float g_rowloss[TS * BB];
__device__ int   g_gctr[NSLOT];                    // per-slot task counters
__device__ unsigned g_bcnt;                        // grid barrier
__device__ unsigned g_bgen;

__device__ __forceinline__ float sigmoidf_(float x) {
    return 1.0f / (1.0f + expf(-x));
}
__device__ __forceinline__ u64 fma2_(u64 a, u64 b, u64 c) {
    u64 d; asm("fma.rn.f32x2 %0, %1, %2, %3;" : "=l"(d) : "l"(a), "l"(b), "l"(c));
    return d;
}
__device__ __forceinline__ u64 pack2_(float x) {
    u64 d; asm("mov.b64 %0, {%1, %1};" : "=l"(d) : "f"(x));
    return d;
}
__device__ __forceinline__ float2 unpack2_(u64 a) {
    float2 f; asm("mov.b64 {%0, %1}, %2;" : "=f"(f.x), "=f"(f.y) : "l"(a));
    return f;
}

// ---------------- init: reset state every replay ------------------------------
__global__ void init_state_kernel() {
    int i = blockIdx.x * blockDim.x + threadIdx.x;
    if (i < BB * HH) { g_h0buf[0][i] = 0.f; g_c0[i] = 0.f; g_c1[i] = 0.f; g_zero[i] = 0.f; }
    if (i < NSLOT) g_gctr[i] = 0;
    if (i == 0) g_bcnt = 0;
}

// ---------------- grid barrier ------------------------------------------------
__device__ __forceinline__ void grid_bar() {
    __syncthreads();
    if (threadIdx.x == 0) {
        __threadfence();
        unsigned gen = *(volatile unsigned*)&g_bgen;
        if (atomicAdd(&g_bcnt, 1u) == GRID_N - 1) {
            *(volatile unsigned*)&g_bcnt = 0;
            __threadfence();
            *(volatile unsigned*)&g_bgen = gen + 1;
        } else {
            while (*(volatile unsigned*)&g_bgen == gen) { __nanosleep(64); }
        }
        __threadfence();
    }
    __syncthreads();
}

// ---------------- pre0 = gather(emb) @ w_ih0 + b0 ----------------------------
__global__ __launch_bounds__(256) void pre0_gemm_kernel(
    const int* __restrict__ sent, const float* __restrict__ wordvec,
    const float* __restrict__ w_ih0, const float* __restrict__ b0)
{
    __shared__ float As[4][64];
    __shared__ float Bs[4][64];
    const int t = blockIdx.y;
    const int colBase = blockIdx.x * 64;
    const int tid = threadIdx.x;
    const int tx = tid & 15, ty = tid >> 4;

    const float* arow = nullptr;
    if (tid < 64) {
        int token = sent[tid * TT + t];
        arow = wordvec + (size_t)token * EE;
    }
    const int bRow = tid >> 6, bCol = tid & 63;

    float acc[4][4] = {};
    for (int kt = 0; kt < 75; kt++) {
        __syncthreads();
        if (tid < 64) {
            float4 a = *(const float4*)(arow + kt * 4);
            As[0][tid] = a.x; As[1][tid] = a.y; As[2][tid] = a.z; As[3][tid] = a.w;
        }
        Bs[bRow][bCol] = w_ih0[(size_t)(kt * 4 + bRow) * G4 + colBase + bCol];
        __syncthreads();
#pragma unroll
        for (int k = 0; k < 4; k++) {
            float4 a4 = *(const float4*)&As[k][ty * 4];
            float4 b4 = *(const float4*)&Bs[k][tx * 4];
            acc[0][0] += a4.x * b4.x; acc[0][1] += a4.x * b4.y; acc[0][2] += a4.x * b4.z; acc[0][3] += a4.x * b4.w;
            acc[1][0] += a4.y * b4.x; acc[1][1] += a4.y * b4.y; acc[1][2] += a4.y * b4.z; acc[1][3] += a4.y * b4.w;
            acc[2][0] += a4.z * b4.x; acc[2][1] += a4.z * b4.y; acc[2][2] += a4.z * b4.z; acc[2][3] += a4.z * b4.w;
            acc[3][0] += a4.w * b4.x; acc[3][1] += a4.w * b4.y; acc[3][2] += a4.w * b4.z; acc[3][3] += a4.w * b4.w;
        }
    }
    float* dst = g_pre0 + ((size_t)t * 64) * G4 + colBase;
#pragma unroll
    for (int i = 0; i < 4; i++) {
        int b_ = ty * 4 + i;
#pragma unroll
        for (int j = 0; j < 4; j++) {
            int c = tx * 4 + j;
            dst[(size_t)b_ * G4 + c] = acc[i][j] + b0[colBase + c];
        }
    }
}

// ---------------- persistent recurrence kernel --------------------------------
// Slot s (0..127), dynamic task queue, 768 tasks of 64x64xK256 per slot.
// f32x2 inner loop + 2-tile-deep LDG pipeline + double-buffered smem (1 sync/kt).
__global__ __launch_bounds__(256, 2) void recur_kernel(
    const float* __restrict__ w_hh0, const float* __restrict__ w_ih1,
    const float* __restrict__ w_hh1, const float* __restrict__ b1)
{
    __shared__ __align__(16) float As[2][16][SPAD];
    __shared__ __align__(16) float Bs[2][16][SPAD];
    __shared__ int s_task;

    const int tid = threadIdx.x;
    const int gthr = blockIdx.x * 256 + tid;

    const int aRow = tid >> 2, aK = (tid & 3) * 4;
    const int bRow = tid >> 4, bCol = (tid & 15) * 4;
    const int tx = tid & 15, ty = tid >> 4;
    const int r0 = ty * 4, c0 = tx * 4;

    for (int s = 0; s < NSLOT; s++) {
        // ---------------- gemm phase ----------------
        for (;;) {
            if (tid == 0) s_task = atomicAdd(&g_gctr[s], 1);
            __syncthreads();
            const int task = s_task;
            __syncthreads();
            if (task >= NTASK) break;

            const float* A; const float* W; float* P;
            bool ok = true;
            if (task < 256) {
                if (s > 126) ok = false;
                const int kc = task >> 6, ct = task & 63;
                A = g_h0buf[s & 1] + kc * 256;
                W = w_hh0 + (size_t)(kc * 256) * G4 + ct * 64;
                P = g_P0[kc] + ct * 64;
            } else {
                if (s < 1) ok = false;
                const int q = task - 256;
                const int kc = q >> 6, ct = q & 63;
                if (kc < 4) {
                    A = g_h0buf[s & 1] + kc * 256;
                    W = w_ih1 + (size_t)(kc * 256) * G4 + ct * 64;
                } else {
                    A = ((s >= 2) ? (g_h1all + (size_t)(s - 2) * BB * HH) : g_zero)
                        + (kc - 4) * 256;
                    W = w_hh1 + (size_t)((kc - 4) * 256) * G4 + ct * 64;
                }
                P = g_P1[kc] + ct * 64;
            }
            if (!ok) continue;

            const float* Aptr = A + (size_t)aRow * HH + aK;
            const float* Wptr = W + (size_t)bRow * G4 + bCol;

            u64 acc[2][4] = {};

            auto STS = [&](int buf, float4 pa, float4 pb) {
                As[buf][aK + 0][aRow] = pa.x; As[buf][aK + 1][aRow] = pa.y;
                As[buf][aK + 2][aRow] = pa.z; As[buf][aK + 3][aRow] = pa.w;
                *(float4*)&Bs[buf][bRow][bCol] = pb;
            };
            auto CP = [&](int buf) {
#pragma unroll
                for (int k = 0; k < 16; k++) {
                    ulonglong2 ap = *(const ulonglong2*)&As[buf][k][r0];
                    float4 b4 = *(const float4*)&Bs[buf][k][c0];
                    u64 w0 = pack2_(b4.x), w1 = pack2_(b4.y);
                    u64 w2 = pack2_(b4.z), w3 = pack2_(b4.w);
                    acc[0][0] = fma2_(ap.x, w0, acc[0][0]);
                    acc[0][1] = fma2_(ap.x, w1, acc[0][1]);
                    acc[0][2] = fma2_(ap.x, w2, acc[0][2]);
                    acc[0][3] = fma2_(ap.x, w3, acc[0][3]);
                    acc[1][0] = fma2_(ap.y, w0, acc[1][0]);
                    acc[1][1] = fma2_(ap.y, w1, acc[1][1]);
                    acc[1][2] = fma2_(ap.y, w2, acc[1][2]);
                    acc[1][3] = fma2_(ap.y, w3, acc[1][3]);
                }
            };

            // prologue: tile0 -> buf0; tile1 held in regs
            float4 pa0 = *(const float4*)(Aptr);
            float4 pb0 = *(const float4*)(Wptr);
            STS(0, pa0, pb0);
            float4 pa1 = *(const float4*)(Aptr + 16);
            float4 pb1 = *(const float4*)(Wptr + (size_t)16 * G4);
            __syncthreads();

            for (int kt = 0; kt < 16; kt += 2) {
                // even iter: compute buf0 (tile kt), STS tile kt+1 -> buf1
                if (kt + 2 < 16) {
                    pa0 = *(const float4*)(Aptr + (kt + 2) * 16);
                    pb0 = *(const float4*)(Wptr + (size_t)(kt + 2) * 16 * G4);
                }
                CP(0);
                STS(1, pa1, pb1);
                __syncthreads();
                // odd iter: compute buf1 (tile kt+1), STS tile kt+2 -> buf0
                if (kt + 3 < 16) {
                    pa1 = *(const float4*)(Aptr + (kt + 3) * 16);
                    pb1 = *(const float4*)(Wptr + (size_t)(kt + 3) * 16 * G4);
                }
                CP(1);
                if (kt + 2 < 16) {
                    STS(0, pa0, pb0);
                }
                __syncthreads();
            }

            // epilogue: rows r0..r0+3 (pairs), cols c0..c0+3
#pragma unroll
            for (int p = 0; p < 2; p++) {
                float2 v0 = unpack2_(acc[p][0]);
                float2 v1 = unpack2_(acc[p][1]);
                float2 v2 = unpack2_(acc[p][2]);
                float2 v3 = unpack2_(acc[p][3]);
                *(float4*)(P + (size_t)(r0 + 2 * p) * G4 + c0) =
                    make_float4(v0.x, v1.x, v2.x, v3.x);
                *(float4*)(P + (size_t)(r0 + 2 * p + 1) * G4 + c0) =
                    make_float4(v0.y, v1.y, v2.y, v3.y);
            }
        }
        grid_bar();

        // ---------------- pointwise phase ----------------
        if (gthr < BB * HH) {
            const int r = gthr >> 10, j = gthr & 1023;
            const size_t base = (size_t)r * G4;
            if (s <= 126) {
                const float* pre = g_pre0 + (size_t)s * BB * G4 + base;
                float gv[4];
#pragma unroll
                for (int g = 0; g < 4; g++) {
                    const int o = g * HH + j;
                    gv[g] = ((g_P0[0][base + o] + g_P0[1][base + o])
                           + (g_P0[2][base + o] + g_P0[3][base + o])) + pre[o];
                }
                float c  = g_c0[gthr];
                float cn = sigmoidf_(gv[1]) * c + sigmoidf_(gv[0]) * tanhf(gv[2]);
                float hn = sigmoidf_(gv[3]) * tanhf(cn);
                g_c0[gthr] = cn;
                g_h0buf[(s + 1) & 1][gthr] = hn;
            }
            if (s >= 1) {
                float gv[4];
#pragma unroll
                for (int g = 0; g < 4; g++) {
                    const int o = g * HH + j;
                    float a = (g_P1[0][base + o] + g_P1[1][base + o])
                            + (g_P1[2][base + o] + g_P1[3][base + o]);
                    float b = (g_P1[4][base + o] + g_P1[5][base + o])
                            + (g_P1[6][base + o] + g_P1[7][base + o]);
                    gv[g] = a + b + b1[o];
                }
                float c  = g_c1[gthr];
                float cn = sigmoidf_(gv[1]) * c + sigmoidf_(gv[0]) * tanhf(gv[2]);
                float hn = sigmoidf_(gv[3]) * tanhf(cn);
                g_c1[gthr] = cn;
                g_h1all[(size_t)(s - 1) * BB * HH + gthr] = hn;
            }
        }
        grid_bar();
    }
}

// ---------------- logits v3: 128x64 tile, 8x4/thread, f32x2 row pairs --------
// grid (157, 64). Rows R = t*64+b in g_h1all order; temp is [b][t][V], 4B-aligned
// -> scalar stores only.
__global__ __launch_bounds__(256) void logits3_kernel(
    const float* __restrict__ w_out, const float* __restrict__ b_out,
    float* __restrict__ temp)
{
    __shared__ __align__(16) float As[16][132];
    __shared__ __align__(16) float Bs[16][68];

    const int mBase = blockIdx.y * 128;
    const int colBase = blockIdx.x * 64;
    const int tid = threadIdx.x;

    // A loader: row 0..127, two k-quads {q, q+2}
    const int aRow = tid & 127;
    const int aQ = tid >> 7;            // 0 or 1
    int gRow = mBase + aRow;
    if (gRow >= MROWS) gRow = MROWS - 1;
    const float* Abase = g_h1all + (size_t)gRow * HH;

    // B loader
    const int bk = tid >> 4, bc4 = tid & 15;
    const int bcol = colBase + bc4 * 4;
    const bool bok = (bcol + 3 < VV);

    // compute mapping
    const int r0 = (tid & 15) * 8;
    const int c0 = (tid >> 4) * 4;

    u64 acc[4][4] = {};

    for (int kt = 0; kt < 64; kt++) {
        __syncthreads();
        {   // load A: 2 float4 per thread
            const int k0 = kt * 16;
            float4 a0 = *(const float4*)(Abase + k0 + aQ * 4);
            float4 a1 = *(const float4*)(Abase + k0 + (aQ + 2) * 4);
            As[aQ * 4 + 0][aRow] = a0.x; As[aQ * 4 + 1][aRow] = a0.y;
            As[aQ * 4 + 2][aRow] = a0.z; As[aQ * 4 + 3][aRow] = a0.w;
            As[aQ * 4 + 8][aRow] = a1.x; As[aQ * 4 + 9][aRow] = a1.y;
            As[aQ * 4 + 10][aRow] = a1.z; As[aQ * 4 + 11][aRow] = a1.w;
            // load B: 1 float4 per thread
            const float* bp = w_out + (size_t)(kt * 16 + bk) * VV + bcol;
            float4 bv;
            if (bok) bv = *(const float4*)bp;
            else {
                bv.x = (bcol + 0 < VV) ? bp[0] : 0.f;
                bv.y = (bcol + 1 < VV) ? bp[1] : 0.f;
                bv.z = (bcol + 2 < VV) ? bp[2] : 0.f;
                bv.w = (bcol + 3 < VV) ? bp[3] : 0.f;
            }
            *(float4*)&Bs[bk][bc4 * 4] = bv;
        }
        __syncthreads();
#pragma unroll
        for (int k = 0; k < 16; k++) {
            ulonglong2 ap0 = *(const ulonglong2*)&As[k][r0];
            ulonglong2 ap1 = *(const ulonglong2*)&As[k][r0 + 4];
            float4 b4 = *(const float4*)&Bs[k][c0];
            u64 w0 = pack2_(b4.x), w1 = pack2_(b4.y);
            u64 w2 = pack2_(b4.z), w3 = pack2_(b4.w);
            acc[0][0] = fma2_(ap0.x, w0, acc[0][0]);
            acc[0][1] = fma2_(ap0.x, w1, acc[0][1]);
            acc[0][2] = fma2_(ap0.x, w2, acc[0][2]);
            acc[0][3] = fma2_(ap0.x, w3, acc[0][3]);
            acc[1][0] = fma2_(ap0.y, w0, acc[1][0]);
            acc[1][1] = fma2_(ap0.y, w1, acc[1][1]);
            acc[1][2] = fma2_(ap0.y, w2, acc[1][2]);
            acc[1][3] = fma2_(ap0.y, w3, acc[1][3]);
            acc[2][0] = fma2_(ap1.x, w0, acc[2][0]);
            acc[2][1] = fma2_(ap1.x, w1, acc[2][1]);
            acc[2][2] = fma2_(ap1.x, w2, acc[2][2]);
            acc[2][3] = fma2_(ap1.x, w3, acc[2][3]);
            acc[3][0] = fma2_(ap1.y, w0, acc[3][0]);
            acc[3][1] = fma2_(ap1.y, w1, acc[3][1]);
            acc[3][2] = fma2_(ap1.y, w2, acc[3][2]);
            acc[3][3] = fma2_(ap1.y, w3, acc[3][3]);
        }
    }

    // epilogue: 4 row-pairs x 4 cols; scalar stores (temp is 4B-aligned)
    const int colT = colBase + c0;
    float bias[4];
#pragma unroll
    for (int c = 0; c < 4; c++)
        bias[c] = (colT + c < VV) ? b_out[colT + c] : 0.f;

#pragma unroll
    for (int p = 0; p < 4; p++) {
        float2 v0 = unpack2_(acc[p][0]);
        float2 v1 = unpack2_(acc[p][1]);
        float2 v2 = unpack2_(acc[p][2]);
        float2 v3 = unpack2_(acc[p][3]);
#pragma unroll
        for (int h = 0; h < 2; h++) {
            const int R = mBase + r0 + 2 * p + h;
            if (R < MROWS) {
                const int t = R >> 6, b_ = R & 63;
                float* dst = temp + ((size_t)b_ * TS + t) * VV + colT;
                float o0 = h ? v0.y : v0.x;
                float o1 = h ? v1.y : v1.x;
                float o2 = h ? v2.y : v2.x;
                float o3 = h ? v3.y : v3.x;
                if (colT + 0 < VV) dst[0] = o0 + bias[0];
                if (colT + 1 < VV) dst[1] = o1 + bias[1];
                if (colT + 2 < VV) dst[2] = o2 + bias[2];
                if (colT + 3 < VV) dst[3] = o3 + bias[3];
            }
        }
    }
}

// ---------------- loss: per-row -logp/length (deterministic) -----------------
__global__ __launch_bounds__(256) void loss_row_kernel(
    const float* __restrict__ temp, const int* __restrict__ sent,
    const int* __restrict__ length)
{
    __shared__ float sm_[256];
    __shared__ float ss[256];
    const int row = blockIdx.x;            // b*127 + t
    const int b = row / TS, t = row % TS;
    const float* x = temp + (size_t)row * VV;
    const int tid = threadIdx.x;

    float m = -1e30f, s = 0.f;
    for (int i = tid; i < VV; i += 256) {
        float v = x[i];
        float M = fmaxf(m, v);
        s = s * expf(m - M) + expf(v - M);
        m = M;
    }
    sm_[tid] = m; ss[tid] = s;
    __syncthreads();
    for (int w = 128; w > 0; w >>= 1) {
        if (tid < w) {
            float m2 = sm_[tid + w], s2 = ss[tid + w];
            float M = fmaxf(sm_[tid], m2);
            ss[tid] = ss[tid] * expf(sm_[tid] - M) + s2 * expf(m2 - M);
            sm_[tid] = M;
        }
        __syncthreads();
    }
    if (tid == 0) {
        int gt = sent[b * TT + t + 1];
        float lse = sm_[0] + logf(ss[0]);
        float res = 0.f;
        if (gt != 0) {
            float lp = x[gt] - lse;
            res = -lp / (float)length[b];
        }
        g_rowloss[row] = res;
    }
}

__global__ __launch_bounds__(256) void loss_final_kernel(float* __restrict__ out) {
    __shared__ float s[256];
    const int tid = threadIdx.x;
    float a = 0.f;
    for (int i = tid; i < TS * BB; i += 256) a += g_rowloss[i];
    s[tid] = a;
    __syncthreads();
    for (int w = 128; w > 0; w >>= 1) {
        if (tid < w) s[tid] += s[tid + w];
        __syncthreads();
    }
    if (tid == 0) out[0] = s[0];
}

// ---------------- host launcher ----------------------------------------------
extern "C" void kernel_launch(void* const* d_in, const int* in_sizes, int n_in,
                              void* d_out, int out_size)
{
    const int*   sent    = (const int*)d_in[0];
    const int*   length  = (const int*)d_in[1];
    const float* wordvec = (const float*)d_in[2];
    const float* w_ih0   = (const float*)d_in[3];
    const float* w_hh0   = (const float*)d_in[4];
    const float* b0      = (const float*)d_in[5];
    const float* w_ih1   = (const float*)d_in[6];
    const float* w_hh1   = (const float*)d_in[7];
    const float* b1      = (const float*)d_in[8];
    const float* w_out   = (const float*)d_in[9];
    const float* b_out   = (const float*)d_in[10];
    float* out = (float*)d_out;

    const long long TEMP_N = (long long)BB * TS * VV;
    int off = ((long long)out_size > TEMP_N) ? (int)((long long)out_size - TEMP_N) : 0;
    float* temp = out + off;

    init_state_kernel<<<256, 256>>>();
    pre0_gemm_kernel<<<dim3(64, TS), 256>>>(sent, wordvec, w_ih0, b0);
    recur_kernel<<<GRID_N, 256>>>(w_hh0, w_ih1, w_hh1, b1);
    logits3_kernel<<<dim3(157, 64), 256>>>(w_out, b_out, temp);
    if (off > 0) {
        loss_row_kernel<<<TS * BB, 256>>>(temp, sent, length);
        loss_final_kernel<<<1, 256>>>(out);
    }
}

// round 14
// speedup vs baseline: 1.1634x; 1.1634x over previous
#include <cuda_runtime.h>
#include <cuda_bf16.h>
#include <math.h>

// Problem constants
#define BB 64
#define TT 128
#define TS 127          // timesteps = T-1
#define VV 10000
#define EE 300
#define HH 1024
#define G4 4096         // 4*H

#define GRID_N 296      // persistent grid: exactly 2 CTAs per SM on 148 SMs
#define NTASK 768       // gemm tasks per slot: L0 64x4=256, L1 64x8=512
#define NSLOT 128
#define SPAD 68         // padded smem row (floats)

typedef unsigned long long u64;

// ---------------- scratch (static device memory; no allocations) -------------
__device__ float g_pre0[(size_t)TS * BB * G4];     // x@w_ih0 + b0, row = t*64+b
__device__ float g_h1all[(size_t)TS * BB * HH];    // all layer-1 hidden states
__device__ float g_h0buf[2][BB * HH];
__device__ float g_c0[BB * HH];
__device__ float g_c1[BB * HH];
__device__ float g_zero[BB * HH];                  // stays zero (never written)
__device__ float g_P0[4][BB * G4];                 // L0 K-chunk partials
__device__ float g_P1[8][BB * G4];                 // L1 K-chunk partials
__device__ float g_rowloss[TS * BB];
__device__ int   g_gctr[NSLOT];                    // per-slot task counters
__device__ unsigned g_bcnt;                        // grid barrier
__device__ unsigned g_bgen;

__device__ __forceinline__ float sigmoidf_(float x) {
    return 1.0f / (1.0f + expf(-x));
}
__device__ __forceinline__ u64 fma2_(u64 a, u64 b, u64 c) {
    u64 d; asm("fma.rn.f32x2 %0, %1, %2, %3;" : "=l"(d) : "l"(a), "l"(b), "l"(c));
    return d;
}
__device__ __forceinline__ u64 pack2_(float x) {
    u64 d; asm("mov.b64 %0, {%1, %1};" : "=l"(d) : "f"(x));
    return d;
}
__device__ __forceinline__ float2 unpack2_(u64 a) {
    float2 f; asm("mov.b64 {%0, %1}, %2;" : "=f"(f.x), "=f"(f.y) : "l"(a));
    return f;
}

// ---------------- init: reset state every replay ------------------------------
__global__ void init_state_kernel() {
    int i = blockIdx.x * blockDim.x + threadIdx.x;
    if (i < BB * HH) { g_h0buf[0][i] = 0.f; g_c0[i] = 0.f; g_c1[i] = 0.f; g_zero[i] = 0.f; }
    if (i < NSLOT) g_gctr[i] = 0;
    if (i == 0) g_bcnt = 0;
}

// ---------------- grid barrier ------------------------------------------------
__device__ __forceinline__ void grid_bar() {
    __syncthreads();
    if (threadIdx.x == 0) {
        __threadfence();
        unsigned gen = *(volatile unsigned*)&g_bgen;
        if (atomicAdd(&g_bcnt, 1u) == GRID_N - 1) {
            *(volatile unsigned*)&g_bcnt = 0;
            __threadfence();
            *(volatile unsigned*)&g_bgen = gen + 1;
        } else {
            while (*(volatile unsigned*)&g_bgen == gen) { __nanosleep(64); }
        }
        __threadfence();
    }
    __syncthreads();
}

// ---------------- pre0 = gather(emb) @ w_ih0 + b0 ----------------------------
__global__ __launch_bounds__(256) void pre0_gemm_kernel(
    const int* __restrict__ sent, const float* __restrict__ wordvec,
    const float* __restrict__ w_ih0, const float* __restrict__ b0)
{
    __shared__ float As[4][64];
    __shared__ float Bs[4][64];
    const int t = blockIdx.y;
    const int colBase = blockIdx.x * 64;
    const int tid = threadIdx.x;
    const int tx = tid & 15, ty = tid >> 4;

    const float* arow = nullptr;
    if (tid < 64) {
        int token = sent[tid * TT + t];
        arow = wordvec + (size_t)token * EE;
    }
    const int bRow = tid >> 6, bCol = tid & 63;

    float acc[4][4] = {};
    for (int kt = 0; kt < 75; kt++) {
        __syncthreads();
        if (tid < 64) {
            float4 a = *(const float4*)(arow + kt * 4);
            As[0][tid] = a.x; As[1][tid] = a.y; As[2][tid] = a.z; As[3][tid] = a.w;
        }
        Bs[bRow][bCol] = w_ih0[(size_t)(kt * 4 + bRow) * G4 + colBase + bCol];
        __syncthreads();
#pragma unroll
        for (int k = 0; k < 4; k++) {
            float4 a4 = *(const float4*)&As[k][ty * 4];
            float4 b4 = *(const float4*)&Bs[k][tx * 4];
            acc[0][0] += a4.x * b4.x; acc[0][1] += a4.x * b4.y; acc[0][2] += a4.x * b4.z; acc[0][3] += a4.x * b4.w;
            acc[1][0] += a4.y * b4.x; acc[1][1] += a4.y * b4.y; acc[1][2] += a4.y * b4.z; acc[1][3] += a4.y * b4.w;
            acc[2][0] += a4.z * b4.x; acc[2][1] += a4.z * b4.y; acc[2][2] += a4.z * b4.z; acc[2][3] += a4.z * b4.w;
            acc[3][0] += a4.w * b4.x; acc[3][1] += a4.w * b4.y; acc[3][2] += a4.w * b4.z; acc[3][3] += a4.w * b4.w;
        }
    }
    float* dst = g_pre0 + ((size_t)t * 64) * G4 + colBase;
#pragma unroll
    for (int i = 0; i < 4; i++) {
        int b_ = ty * 4 + i;
#pragma unroll
        for (int j = 0; j < 4; j++) {
            int c = tx * 4 + j;
            dst[(size_t)b_ * G4 + c] = acc[i][j] + b0[colBase + c];
        }
    }
}

// ---------------- persistent recurrence kernel --------------------------------
// Slot s (0..127), dynamic task queue, 768 tasks of 64x64xK256 per slot.
// f32x2 inner loop + 2-tile-deep LDG pipeline + double-buffered smem (1 sync/kt).
__global__ __launch_bounds__(256, 2) void recur_kernel(
    const float* __restrict__ w_hh0, const float* __restrict__ w_ih1,
    const float* __restrict__ w_hh1, const float* __restrict__ b1)
{
    __shared__ __align__(16) float As[2][16][SPAD];
    __shared__ __align__(16) float Bs[2][16][SPAD];
    __shared__ int s_task;

    const int tid = threadIdx.x;
    const int gthr = blockIdx.x * 256 + tid;

    const int aRow = tid >> 2, aK = (tid & 3) * 4;
    const int bRow = tid >> 4, bCol = (tid & 15) * 4;
    const int tx = tid & 15, ty = tid >> 4;
    const int r0 = ty * 4, c0 = tx * 4;

    for (int s = 0; s < NSLOT; s++) {
        // ---------------- gemm phase ----------------
        for (;;) {
            if (tid == 0) s_task = atomicAdd(&g_gctr[s], 1);
            __syncthreads();
            const int task = s_task;
            __syncthreads();
            if (task >= NTASK) break;

            const float* A; const float* W; float* P;
            bool ok = true;
            if (task < 256) {
                if (s > 126) ok = false;
                const int kc = task >> 6, ct = task & 63;
                A = g_h0buf[s & 1] + kc * 256;
                W = w_hh0 + (size_t)(kc * 256) * G4 + ct * 64;
                P = g_P0[kc] + ct * 64;
            } else {
                if (s < 1) ok = false;
                const int q = task - 256;
                const int kc = q >> 6, ct = q & 63;
                if (kc < 4) {
                    A = g_h0buf[s & 1] + kc * 256;
                    W = w_ih1 + (size_t)(kc * 256) * G4 + ct * 64;
                } else {
                    A = ((s >= 2) ? (g_h1all + (size_t)(s - 2) * BB * HH) : g_zero)
                        + (kc - 4) * 256;
                    W = w_hh1 + (size_t)((kc - 4) * 256) * G4 + ct * 64;
                }
                P = g_P1[kc] + ct * 64;
            }
            if (!ok) continue;

            const float* Aptr = A + (size_t)aRow * HH + aK;
            const float* Wptr = W + (size_t)bRow * G4 + bCol;

            u64 acc[2][4] = {};

            auto STS = [&](int buf, float4 pa, float4 pb) {
                As[buf][aK + 0][aRow] = pa.x; As[buf][aK + 1][aRow] = pa.y;
                As[buf][aK + 2][aRow] = pa.z; As[buf][aK + 3][aRow] = pa.w;
                *(float4*)&Bs[buf][bRow][bCol] = pb;
            };
            auto CP = [&](int buf) {
#pragma unroll
                for (int k = 0; k < 16; k++) {
                    ulonglong2 ap = *(const ulonglong2*)&As[buf][k][r0];
                    float4 b4 = *(const float4*)&Bs[buf][k][c0];
                    u64 w0 = pack2_(b4.x), w1 = pack2_(b4.y);
                    u64 w2 = pack2_(b4.z), w3 = pack2_(b4.w);
                    acc[0][0] = fma2_(ap.x, w0, acc[0][0]);
                    acc[0][1] = fma2_(ap.x, w1, acc[0][1]);
                    acc[0][2] = fma2_(ap.x, w2, acc[0][2]);
                    acc[0][3] = fma2_(ap.x, w3, acc[0][3]);
                    acc[1][0] = fma2_(ap.y, w0, acc[1][0]);
                    acc[1][1] = fma2_(ap.y, w1, acc[1][1]);
                    acc[1][2] = fma2_(ap.y, w2, acc[1][2]);
                    acc[1][3] = fma2_(ap.y, w3, acc[1][3]);
                }
            };

            // prologue: tile0 -> buf0; tile1 held in regs
            float4 pa0 = *(const float4*)(Aptr);
            float4 pb0 = *(const float4*)(Wptr);
            STS(0, pa0, pb0);
            float4 pa1 = *(const float4*)(Aptr + 16);
            float4 pb1 = *(const float4*)(Wptr + (size_t)16 * G4);
            __syncthreads();

            for (int kt = 0; kt < 16; kt += 2) {
                // even iter: compute buf0 (tile kt), STS tile kt+1 -> buf1
                if (kt + 2 < 16) {
                    pa0 = *(const float4*)(Aptr + (kt + 2) * 16);
                    pb0 = *(const float4*)(Wptr + (size_t)(kt + 2) * 16 * G4);
                }
                CP(0);
                STS(1, pa1, pb1);
                __syncthreads();
                // odd iter: compute buf1 (tile kt+1), STS tile kt+2 -> buf0
                if (kt + 3 < 16) {
                    pa1 = *(const float4*)(Aptr + (kt + 3) * 16);
                    pb1 = *(const float4*)(Wptr + (size_t)(kt + 3) * 16 * G4);
                }
                CP(1);
                if (kt + 2 < 16) {
                    STS(0, pa0, pb0);
                }
                __syncthreads();
            }

            // epilogue: rows r0..r0+3 (pairs), cols c0..c0+3
#pragma unroll
            for (int p = 0; p < 2; p++) {
                float2 v0 = unpack2_(acc[p][0]);
                float2 v1 = unpack2_(acc[p][1]);
                float2 v2 = unpack2_(acc[p][2]);
                float2 v3 = unpack2_(acc[p][3]);
                *(float4*)(P + (size_t)(r0 + 2 * p) * G4 + c0) =
                    make_float4(v0.x, v1.x, v2.x, v3.x);
                *(float4*)(P + (size_t)(r0 + 2 * p + 1) * G4 + c0) =
                    make_float4(v0.y, v1.y, v2.y, v3.y);
            }
        }
        grid_bar();

        // ---------------- pointwise phase ----------------
        if (gthr < BB * HH) {
            const int r = gthr >> 10, j = gthr & 1023;
            const size_t base = (size_t)r * G4;
            if (s <= 126) {
                const float* pre = g_pre0 + (size_t)s * BB * G4 + base;
                float gv[4];
#pragma unroll
                for (int g = 0; g < 4; g++) {
                    const int o = g * HH + j;
                    gv[g] = ((g_P0[0][base + o] + g_P0[1][base + o])
                           + (g_P0[2][base + o] + g_P0[3][base + o])) + pre[o];
                }
                float c  = g_c0[gthr];
                float cn = sigmoidf_(gv[1]) * c + sigmoidf_(gv[0]) * tanhf(gv[2]);
                float hn = sigmoidf_(gv[3]) * tanhf(cn);
                g_c0[gthr] = cn;
                g_h0buf[(s + 1) & 1][gthr] = hn;
            }
            if (s >= 1) {
                float gv[4];
#pragma unroll
                for (int g = 0; g < 4; g++) {
                    const int o = g * HH + j;
                    float a = (g_P1[0][base + o] + g_P1[1][base + o])
                            + (g_P1[2][base + o] + g_P1[3][base + o]);
                    float b = (g_P1[4][base + o] + g_P1[5][base + o])
                            + (g_P1[6][base + o] + g_P1[7][base + o]);
                    gv[g] = a + b + b1[o];
                }
                float c  = g_c1[gthr];
                float cn = sigmoidf_(gv[1]) * c + sigmoidf_(gv[0]) * tanhf(gv[2]);
                float hn = sigmoidf_(gv[3]) * tanhf(cn);
                g_c1[gthr] = cn;
                g_h1all[(size_t)(s - 1) * BB * HH + gthr] = hn;
            }
        }
        grid_bar();
    }
}

// ---------------- logits = h1all @ w_out + b_out ------------------------------
// Round-2 proven kernel + register prefetch of the next k-tile (LDG issued
// right after the STS of the current tile, covered by the compute phase).
__global__ __launch_bounds__(256) void logits_gemm_kernel(
    const float* __restrict__ w_out, const float* __restrict__ b_out,
    float* __restrict__ temp)
{
    __shared__ float As[16][64];
    __shared__ float Bs[16][64];
    const int t = blockIdx.y;
    const int colBase = blockIdx.x * 64;
    const int tid = threadIdx.x;
    const int tx = tid & 15, ty = tid >> 4;
    const int aRow = tid >> 2, aK = (tid & 3) * 4;
    const int bRow = tid >> 4, bCol = (tid & 15) * 4;
    const int col = colBase + bCol;
    const bool bok = (col + 3 < VV);

    const float* Aptr = g_h1all + ((size_t)t * 64 + aRow) * HH + aK;
    const float* Bptr = w_out + (size_t)bRow * VV + col;

    auto loadB = [&](int kt, float4& v) {
        const float* bp = Bptr + (size_t)kt * 16 * VV;
        if (bok) v = *(const float4*)bp;
        else {
            v.x = (col + 0 < VV) ? bp[0] : 0.f;
            v.y = (col + 1 < VV) ? bp[1] : 0.f;
            v.z = (col + 2 < VV) ? bp[2] : 0.f;
            v.w = (col + 3 < VV) ? bp[3] : 0.f;
        }
    };

    float4 pa = *(const float4*)(Aptr);
    float4 pb; loadB(0, pb);

    float acc[4][4] = {};
    for (int kt = 0; kt < 64; kt++) {
        __syncthreads();
        As[aK + 0][aRow] = pa.x; As[aK + 1][aRow] = pa.y;
        As[aK + 2][aRow] = pa.z; As[aK + 3][aRow] = pa.w;
        *(float4*)&Bs[bRow][bCol] = pb;
        if (kt < 63) {
            pa = *(const float4*)(Aptr + (kt + 1) * 16);
            loadB(kt + 1, pb);
        }
        __syncthreads();
#pragma unroll
        for (int k = 0; k < 16; k++) {
            float4 a4 = *(const float4*)&As[k][ty * 4];
            float4 b4 = *(const float4*)&Bs[k][tx * 4];
            acc[0][0] += a4.x * b4.x; acc[0][1] += a4.x * b4.y; acc[0][2] += a4.x * b4.z; acc[0][3] += a4.x * b4.w;
            acc[1][0] += a4.y * b4.x; acc[1][1] += a4.y * b4.y; acc[1][2] += a4.y * b4.z; acc[1][3] += a4.y * b4.w;
            acc[2][0] += a4.z * b4.x; acc[2][1] += a4.z * b4.y; acc[2][2] += a4.z * b4.z; acc[2][3] += a4.z * b4.w;
            acc[3][0] += a4.w * b4.x; acc[3][1] += a4.w * b4.y; acc[3][2] += a4.w * b4.z; acc[3][3] += a4.w * b4.w;
        }
    }
#pragma unroll
    for (int i = 0; i < 4; i++) {
        int b_ = ty * 4 + i;
#pragma unroll
        for (int j = 0; j < 4; j++) {
            int c2 = colBase + tx * 4 + j;
            if (c2 < VV)
                temp[((size_t)b_ * TS + t) * VV + c2] = acc[i][j] + b_out[c2];
        }
    }
}

// ---------------- loss: per-row -logp/length (deterministic) -----------------
__global__ __launch_bounds__(256) void loss_row_kernel(
    const float* __restrict__ temp, const int* __restrict__ sent,
    const int* __restrict__ length)
{
    __shared__ float sm_[256];
    __shared__ float ss[256];
    const int row = blockIdx.x;            // b*127 + t
    const int b = row / TS, t = row % TS;
    const float* x = temp + (size_t)row * VV;
    const int tid = threadIdx.x;

    float m = -1e30f, s = 0.f;
    for (int i = tid; i < VV; i += 256) {
        float v = x[i];
        float M = fmaxf(m, v);
        s = s * expf(m - M) + expf(v - M);
        m = M;
    }
    sm_[tid] = m; ss[tid] = s;
    __syncthreads();
    for (int w = 128; w > 0; w >>= 1) {
        if (tid < w) {
            float m2 = sm_[tid + w], s2 = ss[tid + w];
            float M = fmaxf(sm_[tid], m2);
            ss[tid] = ss[tid] * expf(sm_[tid] - M) + s2 * expf(m2 - M);
            sm_[tid] = M;
        }
        __syncthreads();
    }
    if (tid == 0) {
        int gt = sent[b * TT + t + 1];
        float lse = sm_[0] + logf(ss[0]);
        float res = 0.f;
        if (gt != 0) {
            float lp = x[gt] - lse;
            res = -lp / (float)length[b];
        }
        g_rowloss[row] = res;
    }
}

__global__ __launch_bounds__(256) void loss_final_kernel(float* __restrict__ out) {
    __shared__ float s[256];
    const int tid = threadIdx.x;
    float a = 0.f;
    for (int i = tid; i < TS * BB; i += 256) a += g_rowloss[i];
    s[tid] = a;
    __syncthreads();
    for (int w = 128; w > 0; w >>= 1) {
        if (tid < w) s[tid] += s[tid + w];
        __syncthreads();
    }
    if (tid == 0) out[0] = s[0];
}

// ---------------- host launcher ----------------------------------------------
extern "C" void kernel_launch(void* const* d_in, const int* in_sizes, int n_in,
                              void* d_out, int out_size)
{
    const int*   sent    = (const int*)d_in[0];
    const int*   length  = (const int*)d_in[1];
    const float* wordvec = (const float*)d_in[2];
    const float* w_ih0   = (const float*)d_in[3];
    const float* w_hh0   = (const float*)d_in[4];
    const float* b0      = (const float*)d_in[5];
    const float* w_ih1   = (const float*)d_in[6];
    const float* w_hh1   = (const float*)d_in[7];
    const float* b1      = (const float*)d_in[8];
    const float* w_out   = (const float*)d_in[9];
    const float* b_out   = (const float*)d_in[10];
    float* out = (float*)d_out;

    const long long TEMP_N = (long long)BB * TS * VV;
    int off = ((long long)out_size > TEMP_N) ? (int)((long long)out_size - TEMP_N) : 0;
    float* temp = out + off;

    init_state_kernel<<<256, 256>>>();
    pre0_gemm_kernel<<<dim3(64, TS), 256>>>(sent, wordvec, w_ih0, b0);
    recur_kernel<<<GRID_N, 256>>>(w_hh0, w_ih1, w_hh1, b1);
    logits_gemm_kernel<<<dim3(157, TS), 256>>>(w_out, b_out, temp);
    if (off > 0) {
        loss_row_kernel<<<TS * BB, 256>>>(temp, sent, length);
        loss_final_kernel<<<1, 256>>>(out);
    }
}

// round 15
// speedup vs baseline: 1.1729x; 1.0082x over previous
#include <cuda_runtime.h>
#include <cuda_bf16.h>
#include <math.h>

// Problem constants
#define BB 64
#define TT 128
#define TS 127          // timesteps = T-1
#define VV 10000
#define EE 300
#define HH 1024
#define G4 4096         // 4*H

#define GRID_N 296      // persistent grid: exactly 2 CTAs per SM on 148 SMs
#define NTASK 768       // gemm tasks per slot: L0 64x4=256, L1 64x8=512
#define NSLOT 128
#define SPAD 68         // padded smem row (floats)

typedef unsigned long long u64;

// ---------------- scratch (static device memory; no allocations) -------------
__device__ float g_pre0[(size_t)TS * BB * G4];     // x@w_ih0 + b0, row = t*64+b
__device__ float g_h1all[(size_t)TS * BB * HH];    // all layer-1 hidden states
__device__ float g_h0buf[2][BB * HH];
__device__ float g_c0[BB * HH];
__device__ float g_c1[BB * HH];
__device__ float g_zero[BB * HH];                  // stays zero (never written)
__device__ float g_P0[4][BB * G4];                 // L0 K-chunk partials
__device__ float g_P1[8][BB * G4];                 // L1 K-chunk partials
__device__ float g_rowloss[TS * BB];
__device__ int   g_gctr[NSLOT];                    // per-slot task counters
__device__ unsigned g_bcnt;                        // grid barrier
__device__ unsigned g_bgen;

__device__ __forceinline__ float sigmoidf_(float x) {
    return 1.0f / (1.0f + expf(-x));
}
__device__ __forceinline__ u64 fma2_(u64 a, u64 b, u64 c) {
    u64 d; asm("fma.rn.f32x2 %0, %1, %2, %3;" : "=l"(d) : "l"(a), "l"(b), "l"(c));
    return d;
}
__device__ __forceinline__ u64 pack2_(float x) {
    u64 d; asm("mov.b64 %0, {%1, %1};" : "=l"(d) : "f"(x));
    return d;
}
__device__ __forceinline__ float2 unpack2_(u64 a) {
    float2 f; asm("mov.b64 {%0, %1}, %2;" : "=f"(f.x), "=f"(f.y) : "l"(a));
    return f;
}

// ---------------- init: reset state every replay ------------------------------
__global__ void init_state_kernel() {
    int i = blockIdx.x * blockDim.x + threadIdx.x;
    if (i < BB * HH) { g_h0buf[0][i] = 0.f; g_c0[i] = 0.f; g_c1[i] = 0.f; g_zero[i] = 0.f; }
    if (i < NSLOT) g_gctr[i] = 0;
    if (i == 0) g_bcnt = 0;
}

// ---------------- grid barrier ------------------------------------------------
__device__ __forceinline__ void grid_bar() {
    __syncthreads();
    if (threadIdx.x == 0) {
        __threadfence();
        unsigned gen = *(volatile unsigned*)&g_bgen;
        if (atomicAdd(&g_bcnt, 1u) == GRID_N - 1) {
            *(volatile unsigned*)&g_bcnt = 0;
            __threadfence();
            *(volatile unsigned*)&g_bgen = gen + 1;
        } else {
            while (*(volatile unsigned*)&g_bgen == gen) { __nanosleep(64); }
        }
        __threadfence();
    }
    __syncthreads();
}

// ---------------- pre0 = gather(emb) @ w_ih0 + b0 ----------------------------
__global__ __launch_bounds__(256) void pre0_gemm_kernel(
    const int* __restrict__ sent, const float* __restrict__ wordvec,
    const float* __restrict__ w_ih0, const float* __restrict__ b0)
{
    __shared__ float As[4][64];
    __shared__ float Bs[4][64];
    const int t = blockIdx.y;
    const int colBase = blockIdx.x * 64;
    const int tid = threadIdx.x;
    const int tx = tid & 15, ty = tid >> 4;

    const float* arow = nullptr;
    if (tid < 64) {
        int token = sent[tid * TT + t];
        arow = wordvec + (size_t)token * EE;
    }
    const int bRow = tid >> 6, bCol = tid & 63;

    float acc[4][4] = {};
    for (int kt = 0; kt < 75; kt++) {
        __syncthreads();
        if (tid < 64) {
            float4 a = *(const float4*)(arow + kt * 4);
            As[0][tid] = a.x; As[1][tid] = a.y; As[2][tid] = a.z; As[3][tid] = a.w;
        }
        Bs[bRow][bCol] = w_ih0[(size_t)(kt * 4 + bRow) * G4 + colBase + bCol];
        __syncthreads();
#pragma unroll
        for (int k = 0; k < 4; k++) {
            float4 a4 = *(const float4*)&As[k][ty * 4];
            float4 b4 = *(const float4*)&Bs[k][tx * 4];
            acc[0][0] += a4.x * b4.x; acc[0][1] += a4.x * b4.y; acc[0][2] += a4.x * b4.z; acc[0][3] += a4.x * b4.w;
            acc[1][0] += a4.y * b4.x; acc[1][1] += a4.y * b4.y; acc[1][2] += a4.y * b4.z; acc[1][3] += a4.y * b4.w;
            acc[2][0] += a4.z * b4.x; acc[2][1] += a4.z * b4.y; acc[2][2] += a4.z * b4.z; acc[2][3] += a4.z * b4.w;
            acc[3][0] += a4.w * b4.x; acc[3][1] += a4.w * b4.y; acc[3][2] += a4.w * b4.z; acc[3][3] += a4.w * b4.w;
        }
    }
    float* dst = g_pre0 + ((size_t)t * 64) * G4 + colBase;
#pragma unroll
    for (int i = 0; i < 4; i++) {
        int b_ = ty * 4 + i;
#pragma unroll
        for (int j = 0; j < 4; j++) {
            int c = tx * 4 + j;
            dst[(size_t)b_ * G4 + c] = acc[i][j] + b0[colBase + c];
        }
    }
}

// ---------------- persistent recurrence kernel --------------------------------
// Slot s (0..127), dynamic task queue, 768 tasks of 64x64xK256 per slot.
// f32x2 inner loop + 2-tile-deep LDG pipeline + double-buffered smem (1 sync/kt).
__global__ __launch_bounds__(256, 2) void recur_kernel(
    const float* __restrict__ w_hh0, const float* __restrict__ w_ih1,
    const float* __restrict__ w_hh1, const float* __restrict__ b1)
{
    __shared__ __align__(16) float As[2][16][SPAD];
    __shared__ __align__(16) float Bs[2][16][SPAD];
    __shared__ int s_task;

    const int tid = threadIdx.x;
    const int gthr = blockIdx.x * 256 + tid;

    const int aRow = tid >> 2, aK = (tid & 3) * 4;
    const int bRow = tid >> 4, bCol = (tid & 15) * 4;
    const int tx = tid & 15, ty = tid >> 4;
    const int r0 = ty * 4, c0 = tx * 4;

    for (int s = 0; s < NSLOT; s++) {
        // ---------------- gemm phase ----------------
        for (;;) {
            if (tid == 0) s_task = atomicAdd(&g_gctr[s], 1);
            __syncthreads();
            const int task = s_task;
            __syncthreads();
            if (task >= NTASK) break;

            const float* A; const float* W; float* P;
            bool ok = true;
            if (task < 256) {
                if (s > 126) ok = false;
                const int kc = task >> 6, ct = task & 63;
                A = g_h0buf[s & 1] + kc * 256;
                W = w_hh0 + (size_t)(kc * 256) * G4 + ct * 64;
                P = g_P0[kc] + ct * 64;
            } else {
                if (s < 1) ok = false;
                const int q = task - 256;
                const int kc = q >> 6, ct = q & 63;
                if (kc < 4) {
                    A = g_h0buf[s & 1] + kc * 256;
                    W = w_ih1 + (size_t)(kc * 256) * G4 + ct * 64;
                } else {
                    A = ((s >= 2) ? (g_h1all + (size_t)(s - 2) * BB * HH) : g_zero)
                        + (kc - 4) * 256;
                    W = w_hh1 + (size_t)((kc - 4) * 256) * G4 + ct * 64;
                }
                P = g_P1[kc] + ct * 64;
            }
            if (!ok) continue;

            const float* Aptr = A + (size_t)aRow * HH + aK;
            const float* Wptr = W + (size_t)bRow * G4 + bCol;

            u64 acc[2][4] = {};

            auto STS = [&](int buf, float4 pa, float4 pb) {
                As[buf][aK + 0][aRow] = pa.x; As[buf][aK + 1][aRow] = pa.y;
                As[buf][aK + 2][aRow] = pa.z; As[buf][aK + 3][aRow] = pa.w;
                *(float4*)&Bs[buf][bRow][bCol] = pb;
            };
            auto CP = [&](int buf) {
#pragma unroll
                for (int k = 0; k < 16; k++) {
                    ulonglong2 ap = *(const ulonglong2*)&As[buf][k][r0];
                    float4 b4 = *(const float4*)&Bs[buf][k][c0];
                    u64 w0 = pack2_(b4.x), w1 = pack2_(b4.y);
                    u64 w2 = pack2_(b4.z), w3 = pack2_(b4.w);
                    acc[0][0] = fma2_(ap.x, w0, acc[0][0]);
                    acc[0][1] = fma2_(ap.x, w1, acc[0][1]);
                    acc[0][2] = fma2_(ap.x, w2, acc[0][2]);
                    acc[0][3] = fma2_(ap.x, w3, acc[0][3]);
                    acc[1][0] = fma2_(ap.y, w0, acc[1][0]);
                    acc[1][1] = fma2_(ap.y, w1, acc[1][1]);
                    acc[1][2] = fma2_(ap.y, w2, acc[1][2]);
                    acc[1][3] = fma2_(ap.y, w3, acc[1][3]);
                }
            };

            // prologue: tile0 -> buf0; tile1 held in regs
            float4 pa0 = *(const float4*)(Aptr);
            float4 pb0 = *(const float4*)(Wptr);
            STS(0, pa0, pb0);
            float4 pa1 = *(const float4*)(Aptr + 16);
            float4 pb1 = *(const float4*)(Wptr + (size_t)16 * G4);
            __syncthreads();

            for (int kt = 0; kt < 16; kt += 2) {
                // even iter: compute buf0 (tile kt), STS tile kt+1 -> buf1
                if (kt + 2 < 16) {
                    pa0 = *(const float4*)(Aptr + (kt + 2) * 16);
                    pb0 = *(const float4*)(Wptr + (size_t)(kt + 2) * 16 * G4);
                }
                CP(0);
                STS(1, pa1, pb1);
                __syncthreads();
                // odd iter: compute buf1 (tile kt+1), STS tile kt+2 -> buf0
                if (kt + 3 < 16) {
                    pa1 = *(const float4*)(Aptr + (kt + 3) * 16);
                    pb1 = *(const float4*)(Wptr + (size_t)(kt + 3) * 16 * G4);
                }
                CP(1);
                if (kt + 2 < 16) {
                    STS(0, pa0, pb0);
                }
                __syncthreads();
            }

            // epilogue: rows r0..r0+3 (pairs), cols c0..c0+3
#pragma unroll
            for (int p = 0; p < 2; p++) {
                float2 v0 = unpack2_(acc[p][0]);
                float2 v1 = unpack2_(acc[p][1]);
                float2 v2 = unpack2_(acc[p][2]);
                float2 v3 = unpack2_(acc[p][3]);
                *(float4*)(P + (size_t)(r0 + 2 * p) * G4 + c0) =
                    make_float4(v0.x, v1.x, v2.x, v3.x);
                *(float4*)(P + (size_t)(r0 + 2 * p + 1) * G4 + c0) =
                    make_float4(v0.y, v1.y, v2.y, v3.y);
            }
        }
        grid_bar();

        // ---------------- pointwise phase ----------------
        if (gthr < BB * HH) {
            const int r = gthr >> 10, j = gthr & 1023;
            const size_t base = (size_t)r * G4;
            if (s <= 126) {
                const float* pre = g_pre0 + (size_t)s * BB * G4 + base;
                float gv[4];
#pragma unroll
                for (int g = 0; g < 4; g++) {
                    const int o = g * HH + j;
                    gv[g] = ((g_P0[0][base + o] + g_P0[1][base + o])
                           + (g_P0[2][base + o] + g_P0[3][base + o])) + pre[o];
                }
                float c  = g_c0[gthr];
                float cn = sigmoidf_(gv[1]) * c + sigmoidf_(gv[0]) * tanhf(gv[2]);
                float hn = sigmoidf_(gv[3]) * tanhf(cn);
                g_c0[gthr] = cn;
                g_h0buf[(s + 1) & 1][gthr] = hn;
            }
            if (s >= 1) {
                float gv[4];
#pragma unroll
                for (int g = 0; g < 4; g++) {
                    const int o = g * HH + j;
                    float a = (g_P1[0][base + o] + g_P1[1][base + o])
                            + (g_P1[2][base + o] + g_P1[3][base + o]);
                    float b = (g_P1[4][base + o] + g_P1[5][base + o])
                            + (g_P1[6][base + o] + g_P1[7][base + o]);
                    gv[g] = a + b + b1[o];
                }
                float c  = g_c1[gthr];
                float cn = sigmoidf_(gv[1]) * c + sigmoidf_(gv[0]) * tanhf(gv[2]);
                float hn = sigmoidf_(gv[3]) * tanhf(cn);
                g_c1[gthr] = cn;
                g_h1all[(size_t)(s - 1) * BB * HH + gthr] = hn;
            }
        }
        grid_bar();
    }
}

// ---------------- logits = h1all @ w_out + b_out ------------------------------
// Round-14 kernel with the inner loop converted to f32x2 row-pair accumulation.
// Layout/banking identical (As row-pair read = ulonglong2 on 16B-aligned addr);
// B packs on the ALU pipe. Stores stay scalar (temp is 4B-aligned).
__global__ __launch_bounds__(256) void logits_gemm_kernel(
    const float* __restrict__ w_out, const float* __restrict__ b_out,
    float* __restrict__ temp)
{
    __shared__ __align__(16) float As[16][64];
    __shared__ __align__(16) float Bs[16][64];
    const int t = blockIdx.y;
    const int colBase = blockIdx.x * 64;
    const int tid = threadIdx.x;
    const int tx = tid & 15, ty = tid >> 4;
    const int aRow = tid >> 2, aK = (tid & 3) * 4;
    const int bRow = tid >> 4, bCol = (tid & 15) * 4;
    const int col = colBase + bCol;
    const bool bok = (col + 3 < VV);
    const int r0 = ty * 4, c0 = tx * 4;

    const float* Aptr = g_h1all + ((size_t)t * 64 + aRow) * HH + aK;
    const float* Bptr = w_out + (size_t)bRow * VV + col;

    auto loadB = [&](int kt, float4& v) {
        const float* bp = Bptr + (size_t)kt * 16 * VV;
        if (bok) v = *(const float4*)bp;
        else {
            v.x = (col + 0 < VV) ? bp[0] : 0.f;
            v.y = (col + 1 < VV) ? bp[1] : 0.f;
            v.z = (col + 2 < VV) ? bp[2] : 0.f;
            v.w = (col + 3 < VV) ? bp[3] : 0.f;
        }
    };

    float4 pa = *(const float4*)(Aptr);
    float4 pb; loadB(0, pb);

    u64 acc[2][4] = {};
    for (int kt = 0; kt < 64; kt++) {
        __syncthreads();
        As[aK + 0][aRow] = pa.x; As[aK + 1][aRow] = pa.y;
        As[aK + 2][aRow] = pa.z; As[aK + 3][aRow] = pa.w;
        *(float4*)&Bs[bRow][bCol] = pb;
        if (kt < 63) {
            pa = *(const float4*)(Aptr + (kt + 1) * 16);
            loadB(kt + 1, pb);
        }
        __syncthreads();
#pragma unroll
        for (int k = 0; k < 16; k++) {
            ulonglong2 ap = *(const ulonglong2*)&As[k][r0];
            float4 b4 = *(const float4*)&Bs[k][c0];
            u64 w0 = pack2_(b4.x), w1 = pack2_(b4.y);
            u64 w2 = pack2_(b4.z), w3 = pack2_(b4.w);
            acc[0][0] = fma2_(ap.x, w0, acc[0][0]);
            acc[0][1] = fma2_(ap.x, w1, acc[0][1]);
            acc[0][2] = fma2_(ap.x, w2, acc[0][2]);
            acc[0][3] = fma2_(ap.x, w3, acc[0][3]);
            acc[1][0] = fma2_(ap.y, w0, acc[1][0]);
            acc[1][1] = fma2_(ap.y, w1, acc[1][1]);
            acc[1][2] = fma2_(ap.y, w2, acc[1][2]);
            acc[1][3] = fma2_(ap.y, w3, acc[1][3]);
        }
    }

    // epilogue: row pairs (r0+2p, r0+2p+1), cols c0..c0+3; scalar stores
#pragma unroll
    for (int p = 0; p < 2; p++) {
        float2 v0 = unpack2_(acc[p][0]);
        float2 v1 = unpack2_(acc[p][1]);
        float2 v2 = unpack2_(acc[p][2]);
        float2 v3 = unpack2_(acc[p][3]);
#pragma unroll
        for (int h = 0; h < 2; h++) {
            const int b_ = r0 + 2 * p + h;
            float o0 = h ? v0.y : v0.x;
            float o1 = h ? v1.y : v1.x;
            float o2 = h ? v2.y : v2.x;
            float o3 = h ? v3.y : v3.x;
            float* dst = temp + ((size_t)b_ * TS + t) * VV + colBase + c0;
            if (colBase + c0 + 0 < VV) dst[0] = o0 + b_out[colBase + c0 + 0];
            if (colBase + c0 + 1 < VV) dst[1] = o1 + b_out[colBase + c0 + 1];
            if (colBase + c0 + 2 < VV) dst[2] = o2 + b_out[colBase + c0 + 2];
            if (colBase + c0 + 3 < VV) dst[3] = o3 + b_out[colBase + c0 + 3];
        }
    }
}

// ---------------- loss: per-row -logp/length (deterministic) -----------------
__global__ __launch_bounds__(256) void loss_row_kernel(
    const float* __restrict__ temp, const int* __restrict__ sent,
    const int* __restrict__ length)
{
    __shared__ float sm_[256];
    __shared__ float ss[256];
    const int row = blockIdx.x;            // b*127 + t
    const int b = row / TS, t = row % TS;
    const float* x = temp + (size_t)row * VV;
    const int tid = threadIdx.x;

    float m = -1e30f, s = 0.f;
    for (int i = tid; i < VV; i += 256) {
        float v = x[i];
        float M = fmaxf(m, v);
        s = s * expf(m - M) + expf(v - M);
        m = M;
    }
    sm_[tid] = m; ss[tid] = s;
    __syncthreads();
    for (int w = 128; w > 0; w >>= 1) {
        if (tid < w) {
            float m2 = sm_[tid + w], s2 = ss[tid + w];
            float M = fmaxf(sm_[tid], m2);
            ss[tid] = ss[tid] * expf(sm_[tid] - M) + s2 * expf(m2 - M);
            sm_[tid] = M;
        }
        __syncthreads();
    }
    if (tid == 0) {
        int gt = sent[b * TT + t + 1];
        float lse = sm_[0] + logf(ss[0]);
        float res = 0.f;
        if (gt != 0) {
            float lp = x[gt] - lse;
            res = -lp / (float)length[b];
        }
        g_rowloss[row] = res;
    }
}

__global__ __launch_bounds__(256) void loss_final_kernel(float* __restrict__ out) {
    __shared__ float s[256];
    const int tid = threadIdx.x;
    float a = 0.f;
    for (int i = tid; i < TS * BB; i += 256) a += g_rowloss[i];
    s[tid] = a;
    __syncthreads();
    for (int w = 128; w > 0; w >>= 1) {
        if (tid < w) s[tid] += s[tid + w];
        __syncthreads();
    }
    if (tid == 0) out[0] = s[0];
}

// ---------------- host launcher ----------------------------------------------
extern "C" void kernel_launch(void* const* d_in, const int* in_sizes, int n_in,
                              void* d_out, int out_size)
{
    const int*   sent    = (const int*)d_in[0];
    const int*   length  = (const int*)d_in[1];
    const float* wordvec = (const float*)d_in[2];
    const float* w_ih0   = (const float*)d_in[3];
    const float* w_hh0   = (const float*)d_in[4];
    const float* b0      = (const float*)d_in[5];
    const float* w_ih1   = (const float*)d_in[6];
    const float* w_hh1   = (const float*)d_in[7];
    const float* b1      = (const float*)d_in[8];
    const float* w_out   = (const float*)d_in[9];
    const float* b_out   = (const float*)d_in[10];
    float* out = (float*)d_out;

    const long long TEMP_N = (long long)BB * TS * VV;
    int off = ((long long)out_size > TEMP_N) ? (int)((long long)out_size - TEMP_N) : 0;
    float* temp = out + off;

    init_state_kernel<<<256, 256>>>();
    pre0_gemm_kernel<<<dim3(64, TS), 256>>>(sent, wordvec, w_ih0, b0);
    recur_kernel<<<GRID_N, 256>>>(w_hh0, w_ih1, w_hh1, b1);
    logits_gemm_kernel<<<dim3(157, TS), 256>>>(w_out, b_out, temp);
    if (off > 0) {
        loss_row_kernel<<<TS * BB, 256>>>(temp, sent, length);
        loss_final_kernel<<<1, 256>>>(out);
    }
}